// round 2
// baseline (speedup 1.0000x reference)
#include <cuda_runtime.h>
#include <math.h>

#define B_SZ 256
#define T_ENC 336
#define F_IN 16
#define U_SZ 512
#define G4 2048
#define HORIZON 48

#define BM 64
#define BK 16
#define NTHREADS 128

// ---------------- persistent device scratch (static, allocation-free) ----------------
__device__ float g_out0[(size_t)B_SZ * T_ENC * U_SZ];  // encoder layer0 h_t for all t (176 MB)
__device__ float g_h1[2][B_SZ * U_SZ];                 // layer1/decoder-layer1 h ping-pong
__device__ float g_c0[B_SZ * U_SZ];                    // layer0 / dec-layer0 cell state
__device__ float g_c1[B_SZ * U_SZ];                    // layer1 / dec-layer1 cell state
__device__ float g_dh0[2][B_SZ * U_SZ];                // decoder layer0 h ping-pong
__device__ float g_x[B_SZ];                            // decoder scalar input
__device__ float g_zero[B_SZ * U_SZ];                  // never written: stays zero across replays

__device__ __forceinline__ float sigf(float x) { return 1.0f / (1.0f + expf(-x)); }

// ---------------------------------------------------------------------------
// Fused LSTM step:
//   z[256, 2048] = A0[256,K0] @ W0[K0,2048] + A1[256,K1] @ W1[K1,2048] + bias
//   i,f,g,o = split(z); c = f*c + i*tanh-gate; h = o*tanh(c)
// Block tile: 64 batch rows x (4 gates x 16 units)  ->  grid (U/16, B/64) = (32,4)
// B-matrix column within tile n' = gate*16 + uoff maps to W column gate*512 + u.
// After GEMM, the z-tile lives in smem so gates + state update are done in-block.
// ---------------------------------------------------------------------------
__global__ __launch_bounds__(NTHREADS) void lstm_step(
    const float* __restrict__ A0, int lda0, int K0, const float* __restrict__ W0,
    const float* __restrict__ A1, int lda1, int K1, const float* __restrict__ W1,
    const float* __restrict__ bias,
    float* __restrict__ c_state,                // [B*U], in-place
    float* __restrict__ h_out, int ldh)         // h_out[b*ldh + u]
{
    __shared__ float As[BK][BM];
    __shared__ float Bs[BK][64];
    __shared__ float Zs[64][65];

    const int tid = threadIdx.x;
    const int tx = tid & 15;       // 0..15 -> 4 output cols each
    const int ty = tid >> 4;       // 0..7  -> 8 output rows each
    const int block_m = blockIdx.y * BM;
    const int block_u = blockIdx.x;          // 16-unit chunk index

    // B loader mapping: tile col n' = tx*4 .. +3 (stays within one gate group of 16)
    const int bn   = tx * 4;
    const int gate = bn >> 4;
    const int wcol = gate * 512 + block_u * 16 + (bn & 15);

    // A loader mapping: each thread loads 8 consecutive k of one row
    const int ar = tid >> 1;            // 0..63
    const int ak = (tid & 1) * 8;       // 0 or 8

    float acc[8][4];
#pragma unroll
    for (int i = 0; i < 8; i++)
#pragma unroll
        for (int j = 0; j < 4; j++) acc[i][j] = 0.f;

#pragma unroll 1
    for (int seg = 0; seg < 2; ++seg) {
        const float* A  = seg ? A1 : A0;
        const float* W  = seg ? W1 : W0;
        const int lda   = seg ? lda1 : lda0;
        const int K     = seg ? K1 : K0;
        for (int k0 = 0; k0 < K; k0 += BK) {
            // ---- load A tile (64 x 16), transposed into As[k][m] ----
            const float* a_base = A + (size_t)(block_m + ar) * lda + k0 + ak;
            if (k0 + BK <= K) {
                float4 v0 = *(const float4*)(a_base);
                float4 v1 = *(const float4*)(a_base + 4);
                As[ak + 0][ar] = v0.x; As[ak + 1][ar] = v0.y;
                As[ak + 2][ar] = v0.z; As[ak + 3][ar] = v0.w;
                As[ak + 4][ar] = v1.x; As[ak + 5][ar] = v1.y;
                As[ak + 6][ar] = v1.z; As[ak + 7][ar] = v1.w;
            } else {
#pragma unroll
                for (int j = 0; j < 8; ++j) {
                    int kg = k0 + ak + j;
                    As[ak + j][ar] = (kg < K) ? a_base[j] : 0.f;
                }
            }
            // ---- load B tile (16 x 64): 2 rows of float4 per thread ----
#pragma unroll
            for (int r = 0; r < 2; ++r) {
                int kk = ty + r * 8;
                int kg = k0 + kk;
                float4 wv = make_float4(0.f, 0.f, 0.f, 0.f);
                if (kg < K) wv = *(const float4*)(W + (size_t)kg * G4 + wcol);
                *(float4*)&Bs[kk][bn] = wv;
            }
            __syncthreads();
#pragma unroll
            for (int kk = 0; kk < BK; ++kk) {
                float4 a0 = *(const float4*)&As[kk][ty * 8];
                float4 a1 = *(const float4*)&As[kk][ty * 8 + 4];
                float4 bv = *(const float4*)&Bs[kk][tx * 4];
                float ar_[8] = {a0.x, a0.y, a0.z, a0.w, a1.x, a1.y, a1.z, a1.w};
                float br_[4] = {bv.x, bv.y, bv.z, bv.w};
#pragma unroll
                for (int i = 0; i < 8; i++)
#pragma unroll
                    for (int j = 0; j < 4; j++)
                        acc[i][j] += ar_[i] * br_[j];
            }
            __syncthreads();
        }
    }

    // ---- epilogue: z-tile -> smem (bias added) ----
#pragma unroll
    for (int j = 0; j < 4; j++) {
        float bb = bias[wcol + j];
#pragma unroll
        for (int i = 0; i < 8; i++)
            Zs[ty * 8 + i][bn + j] = acc[i][j] + bb;
    }
    __syncthreads();

    // ---- gates + state update: 128 threads x 8 (b,u) pairs = 64x16 tile ----
    const int uo  = tid & 15;
    const int b0r = (tid >> 4) * 8;
    const int gu  = block_u * 16 + uo;
#pragma unroll
    for (int i = 0; i < 8; ++i) {
        int br = b0r + i;
        float zi = Zs[br][ 0 + uo];
        float zf = Zs[br][16 + uo];
        float zg = Zs[br][32 + uo];
        float zo = Zs[br][48 + uo];
        float ig = sigf(zi);
        float fg = sigf(zf);
        float gg = tanhf(zg);
        float og = sigf(zo);
        size_t cidx = (size_t)(block_m + br) * U_SZ + gu;
        float cn = fg * c_state[cidx] + ig * gg;
        c_state[cidx] = cn;
        h_out[(size_t)(block_m + br) * ldh + gu] = og * tanhf(cn);
    }
}

// y[b] = h1[b,:] . Wd + bd ; write to out[b,HORIZON] column d and to g_x
__global__ __launch_bounds__(128) void proj_kernel(
    const float* __restrict__ h1, const float* __restrict__ Wd,
    const float* __restrict__ bd, float* __restrict__ x,
    float* __restrict__ out, int d)
{
    int w = (blockIdx.x * blockDim.x + threadIdx.x) >> 5;
    int lane = threadIdx.x & 31;
    if (w >= B_SZ) return;
    const float* hr = h1 + (size_t)w * U_SZ;
    float s = 0.f;
#pragma unroll 4
    for (int k = lane; k < U_SZ; k += 32) s += hr[k] * Wd[k];
#pragma unroll
    for (int o = 16; o > 0; o >>= 1) s += __shfl_down_sync(0xffffffffu, s, o);
    if (lane == 0) {
        float y = s + bd[0];
        x[w] = y;
        out[(size_t)w * HORIZON + d] = y;
    }
}

// per-launch state reset (graph replays must be deterministic)
__global__ void init_kernel(const float* __restrict__ dec_in)
{
    int i = blockIdx.x * blockDim.x + threadIdx.x;
    if (i < B_SZ * U_SZ) {
        g_c0[i] = 0.f;
        g_c1[i] = 0.f;
        g_h1[0][i] = 0.f;
    }
    if (i < B_SZ) g_x[i] = dec_in[i];
}

extern "C" void kernel_launch(void* const* d_in, const int* in_sizes, int n_in,
                              void* d_out, int out_size)
{
    const float* enc    = (const float*)d_in[0];
    const float* dec_in = (const float*)d_in[1];
    const float* eWx0   = (const float*)d_in[2];
    const float* eWh0   = (const float*)d_in[3];
    const float* eb0    = (const float*)d_in[4];
    const float* eWx1   = (const float*)d_in[5];
    const float* eWh1   = (const float*)d_in[6];
    const float* eb1    = (const float*)d_in[7];
    const float* dWx0   = (const float*)d_in[8];
    const float* dWh0   = (const float*)d_in[9];
    const float* db0    = (const float*)d_in[10];
    const float* dWx1   = (const float*)d_in[11];
    const float* dWh1   = (const float*)d_in[12];
    const float* db1    = (const float*)d_in[13];
    const float* Wd     = (const float*)d_in[14];
    const float* bd     = (const float*)d_in[15];
    float* out = (float*)d_out;

    float *p_out0, *p_h1, *p_c0, *p_c1, *p_dh0, *p_x, *p_zero;
    cudaGetSymbolAddress((void**)&p_out0, g_out0);
    cudaGetSymbolAddress((void**)&p_h1,   g_h1);
    cudaGetSymbolAddress((void**)&p_c0,   g_c0);
    cudaGetSymbolAddress((void**)&p_c1,   g_c1);
    cudaGetSymbolAddress((void**)&p_dh0,  g_dh0);
    cudaGetSymbolAddress((void**)&p_x,    g_x);
    cudaGetSymbolAddress((void**)&p_zero, g_zero);
    float* h1p[2]  = {p_h1,  p_h1  + (size_t)B_SZ * U_SZ};
    float* dh0p[2] = {p_dh0, p_dh0 + (size_t)B_SZ * U_SZ};

    const dim3 grid(U_SZ / 16, B_SZ / BM);   // (32, 4)

    init_kernel<<<(B_SZ * U_SZ + 255) / 256, 256>>>(dec_in);

    // ---------------- encoder layer 0 ----------------
    for (int t = 0; t < T_ENC; ++t) {
        const float* hprev = (t == 0) ? p_zero : (p_out0 + (size_t)(t - 1) * U_SZ);
        int ldah = (t == 0) ? U_SZ : (T_ENC * U_SZ);
        lstm_step<<<grid, NTHREADS>>>(
            enc + (size_t)t * F_IN, T_ENC * F_IN, F_IN, eWx0,
            hprev, ldah, U_SZ, eWh0,
            eb0, p_c0, p_out0 + (size_t)t * U_SZ, T_ENC * U_SZ);
    }

    // ---------------- encoder layer 1 ----------------
    for (int t = 0; t < T_ENC; ++t) {
        lstm_step<<<grid, NTHREADS>>>(
            p_out0 + (size_t)t * U_SZ, T_ENC * U_SZ, U_SZ, eWx1,
            h1p[t & 1], U_SZ, U_SZ, eWh1,
            eb1, p_c1, h1p[(t + 1) & 1], U_SZ);
    }
    // after loop: eh1 is in h1p[0] (336 even), ec1 in g_c1, eh0 = out0[:,335,:], ec0 in g_c0

    // ---------------- decoder ----------------
    for (int d = 0; d < HORIZON; ++d) {
        const float* h0in = (d == 0) ? (p_out0 + (size_t)(T_ENC - 1) * U_SZ) : dh0p[d & 1];
        int lh0 = (d == 0) ? (T_ENC * U_SZ) : U_SZ;
        // layer 0: x is scalar per batch row (K0 = 1)
        lstm_step<<<grid, NTHREADS>>>(
            p_x, 1, 1, dWx0,
            h0in, lh0, U_SZ, dWh0,
            db0, p_c0, dh0p[(d & 1) ^ 1], U_SZ);
        // layer 1: input is new h0
        lstm_step<<<grid, NTHREADS>>>(
            dh0p[(d & 1) ^ 1], U_SZ, U_SZ, dWx1,
            h1p[d & 1], U_SZ, U_SZ, dWh1,
            db1, p_c1, h1p[(d + 1) & 1], U_SZ);
        // projection -> output column d and next x
        proj_kernel<<<(B_SZ * 32) / 128, 128>>>(h1p[(d + 1) & 1], Wd, bd, p_x, out, d);
    }
}

// round 3
// speedup vs baseline: 1.0019x; 1.0019x over previous
#include <cuda_runtime.h>
#include <math.h>

#define B_SZ 256
#define T_ENC 336
#define F_IN 16
#define U_SZ 512
#define G4 2048
#define HORIZON 48

#define BM 64
#define BK 16
#define NTHREADS 128

// ---------------- persistent device scratch (static, allocation-free) ----------------
__device__ float g_out0[(size_t)B_SZ * T_ENC * U_SZ];  // encoder layer0 h_t for all t (176 MB)
__device__ float g_h1[2][B_SZ * U_SZ];                 // layer1/decoder-layer1 h ping-pong
__device__ float g_c0[B_SZ * U_SZ];                    // layer0 / dec-layer0 cell state
__device__ float g_c1[B_SZ * U_SZ];                    // layer1 / dec-layer1 cell state
__device__ float g_dh0[2][B_SZ * U_SZ];                // decoder layer0 h ping-pong
__device__ float g_x[B_SZ];                            // decoder scalar input
__device__ float g_zero[B_SZ * U_SZ];                  // never written: stays zero across replays

__device__ __forceinline__ float sigf(float x) { return 1.0f / (1.0f + expf(-x)); }

// ---------------------------------------------------------------------------
// Fused LSTM step:
//   z[256, 2048] = A0[256,K0] @ W0[K0,2048] + A1[256,K1] @ W1[K1,2048] + bias
//   i,f,g,o = split(z); c = f*c + i*tanh-gate; h = o*tanh(c)
// Block tile: 64 batch rows x (4 gates x 16 units)  ->  grid (U/16, B/64) = (32,4)
// B-matrix column within tile n' = gate*16 + uoff maps to W column gate*512 + u.
// After GEMM, the z-tile lives in smem so gates + state update are done in-block.
// ---------------------------------------------------------------------------
__global__ __launch_bounds__(NTHREADS) void lstm_step(
    const float* __restrict__ A0, int lda0, int K0, const float* __restrict__ W0,
    const float* __restrict__ A1, int lda1, int K1, const float* __restrict__ W1,
    const float* __restrict__ bias,
    float* __restrict__ c_state,                // [B*U], in-place
    float* __restrict__ h_out, int ldh)         // h_out[b*ldh + u]
{
    __shared__ float As[BK][BM];
    __shared__ float Bs[BK][64];
    __shared__ float Zs[64][65];

    const int tid = threadIdx.x;
    const int tx = tid & 15;       // 0..15 -> 4 output cols each
    const int ty = tid >> 4;       // 0..7  -> 8 output rows each
    const int block_m = blockIdx.y * BM;
    const int block_u = blockIdx.x;          // 16-unit chunk index

    // B loader mapping: tile col n' = tx*4 .. +3 (stays within one gate group of 16)
    const int bn   = tx * 4;
    const int gate = bn >> 4;
    const int wcol = gate * 512 + block_u * 16 + (bn & 15);

    // A loader mapping: each thread loads 8 consecutive k of one row
    const int ar = tid >> 1;            // 0..63
    const int ak = (tid & 1) * 8;       // 0 or 8

    float acc[8][4];
#pragma unroll
    for (int i = 0; i < 8; i++)
#pragma unroll
        for (int j = 0; j < 4; j++) acc[i][j] = 0.f;

#pragma unroll 1
    for (int seg = 0; seg < 2; ++seg) {
        const float* A  = seg ? A1 : A0;
        const float* W  = seg ? W1 : W0;
        const int lda   = seg ? lda1 : lda0;
        const int K     = seg ? K1 : K0;
        for (int k0 = 0; k0 < K; k0 += BK) {
            // ---- load A tile (64 x 16), transposed into As[k][m] ----
            const float* a_base = A + (size_t)(block_m + ar) * lda + k0 + ak;
            if (k0 + BK <= K) {
                float4 v0 = *(const float4*)(a_base);
                float4 v1 = *(const float4*)(a_base + 4);
                As[ak + 0][ar] = v0.x; As[ak + 1][ar] = v0.y;
                As[ak + 2][ar] = v0.z; As[ak + 3][ar] = v0.w;
                As[ak + 4][ar] = v1.x; As[ak + 5][ar] = v1.y;
                As[ak + 6][ar] = v1.z; As[ak + 7][ar] = v1.w;
            } else {
#pragma unroll
                for (int j = 0; j < 8; ++j) {
                    int kg = k0 + ak + j;
                    As[ak + j][ar] = (kg < K) ? a_base[j] : 0.f;
                }
            }
            // ---- load B tile (16 x 64): 2 rows of float4 per thread ----
#pragma unroll
            for (int r = 0; r < 2; ++r) {
                int kk = ty + r * 8;
                int kg = k0 + kk;
                float4 wv = make_float4(0.f, 0.f, 0.f, 0.f);
                if (kg < K) wv = *(const float4*)(W + (size_t)kg * G4 + wcol);
                *(float4*)&Bs[kk][bn] = wv;
            }
            __syncthreads();
#pragma unroll
            for (int kk = 0; kk < BK; ++kk) {
                float4 a0 = *(const float4*)&As[kk][ty * 8];
                float4 a1 = *(const float4*)&As[kk][ty * 8 + 4];
                float4 bv = *(const float4*)&Bs[kk][tx * 4];
                float ar_[8] = {a0.x, a0.y, a0.z, a0.w, a1.x, a1.y, a1.z, a1.w};
                float br_[4] = {bv.x, bv.y, bv.z, bv.w};
#pragma unroll
                for (int i = 0; i < 8; i++)
#pragma unroll
                    for (int j = 0; j < 4; j++)
                        acc[i][j] += ar_[i] * br_[j];
            }
            __syncthreads();
        }
    }

    // ---- epilogue: z-tile -> smem (bias added) ----
#pragma unroll
    for (int j = 0; j < 4; j++) {
        float bb = bias[wcol + j];
#pragma unroll
        for (int i = 0; i < 8; i++)
            Zs[ty * 8 + i][bn + j] = acc[i][j] + bb;
    }
    __syncthreads();

    // ---- gates + state update: 128 threads x 8 (b,u) pairs = 64x16 tile ----
    const int uo  = tid & 15;
    const int b0r = (tid >> 4) * 8;
    const int gu  = block_u * 16 + uo;
#pragma unroll
    for (int i = 0; i < 8; ++i) {
        int br = b0r + i;
        float zi = Zs[br][ 0 + uo];
        float zf = Zs[br][16 + uo];
        float zg = Zs[br][32 + uo];
        float zo = Zs[br][48 + uo];
        float ig = sigf(zi);
        float fg = sigf(zf);
        float gg = tanhf(zg);
        float og = sigf(zo);
        size_t cidx = (size_t)(block_m + br) * U_SZ + gu;
        float cn = fg * c_state[cidx] + ig * gg;
        c_state[cidx] = cn;
        h_out[(size_t)(block_m + br) * ldh + gu] = og * tanhf(cn);
    }
}

// y[b] = h1[b,:] . Wd + bd ; write to out[b,HORIZON] column d and to g_x
__global__ __launch_bounds__(128) void proj_kernel(
    const float* __restrict__ h1, const float* __restrict__ Wd,
    const float* __restrict__ bd, float* __restrict__ x,
    float* __restrict__ out, int d)
{
    int w = (blockIdx.x * blockDim.x + threadIdx.x) >> 5;
    int lane = threadIdx.x & 31;
    if (w >= B_SZ) return;
    const float* hr = h1 + (size_t)w * U_SZ;
    float s = 0.f;
#pragma unroll 4
    for (int k = lane; k < U_SZ; k += 32) s += hr[k] * Wd[k];
#pragma unroll
    for (int o = 16; o > 0; o >>= 1) s += __shfl_down_sync(0xffffffffu, s, o);
    if (lane == 0) {
        float y = s + bd[0];
        x[w] = y;
        out[(size_t)w * HORIZON + d] = y;
    }
}

// per-launch state reset (graph replays must be deterministic)
__global__ void init_kernel(const float* __restrict__ dec_in)
{
    int i = blockIdx.x * blockDim.x + threadIdx.x;
    if (i < B_SZ * U_SZ) {
        g_c0[i] = 0.f;
        g_c1[i] = 0.f;
        g_h1[0][i] = 0.f;
    }
    if (i < B_SZ) g_x[i] = dec_in[i];
}

extern "C" void kernel_launch(void* const* d_in, const int* in_sizes, int n_in,
                              void* d_out, int out_size)
{
    const float* enc    = (const float*)d_in[0];
    const float* dec_in = (const float*)d_in[1];
    const float* eWx0   = (const float*)d_in[2];
    const float* eWh0   = (const float*)d_in[3];
    const float* eb0    = (const float*)d_in[4];
    const float* eWx1   = (const float*)d_in[5];
    const float* eWh1   = (const float*)d_in[6];
    const float* eb1    = (const float*)d_in[7];
    const float* dWx0   = (const float*)d_in[8];
    const float* dWh0   = (const float*)d_in[9];
    const float* db0    = (const float*)d_in[10];
    const float* dWx1   = (const float*)d_in[11];
    const float* dWh1   = (const float*)d_in[12];
    const float* db1    = (const float*)d_in[13];
    const float* Wd     = (const float*)d_in[14];
    const float* bd     = (const float*)d_in[15];
    float* out = (float*)d_out;

    float *p_out0, *p_h1, *p_c0, *p_c1, *p_dh0, *p_x, *p_zero;
    cudaGetSymbolAddress((void**)&p_out0, g_out0);
    cudaGetSymbolAddress((void**)&p_h1,   g_h1);
    cudaGetSymbolAddress((void**)&p_c0,   g_c0);
    cudaGetSymbolAddress((void**)&p_c1,   g_c1);
    cudaGetSymbolAddress((void**)&p_dh0,  g_dh0);
    cudaGetSymbolAddress((void**)&p_x,    g_x);
    cudaGetSymbolAddress((void**)&p_zero, g_zero);
    float* h1p[2]  = {p_h1,  p_h1  + (size_t)B_SZ * U_SZ};
    float* dh0p[2] = {p_dh0, p_dh0 + (size_t)B_SZ * U_SZ};

    const dim3 grid(U_SZ / 16, B_SZ / BM);   // (32, 4)

    init_kernel<<<(B_SZ * U_SZ + 255) / 256, 256>>>(dec_in);

    // ---------------- encoder layer 0 ----------------
    for (int t = 0; t < T_ENC; ++t) {
        const float* hprev = (t == 0) ? p_zero : (p_out0 + (size_t)(t - 1) * U_SZ);
        int ldah = (t == 0) ? U_SZ : (T_ENC * U_SZ);
        lstm_step<<<grid, NTHREADS>>>(
            enc + (size_t)t * F_IN, T_ENC * F_IN, F_IN, eWx0,
            hprev, ldah, U_SZ, eWh0,
            eb0, p_c0, p_out0 + (size_t)t * U_SZ, T_ENC * U_SZ);
    }

    // ---------------- encoder layer 1 ----------------
    for (int t = 0; t < T_ENC; ++t) {
        lstm_step<<<grid, NTHREADS>>>(
            p_out0 + (size_t)t * U_SZ, T_ENC * U_SZ, U_SZ, eWx1,
            h1p[t & 1], U_SZ, U_SZ, eWh1,
            eb1, p_c1, h1p[(t + 1) & 1], U_SZ);
    }
    // after loop: eh1 is in h1p[0] (336 even), ec1 in g_c1, eh0 = out0[:,335,:], ec0 in g_c0

    // ---------------- decoder ----------------
    for (int d = 0; d < HORIZON; ++d) {
        const float* h0in = (d == 0) ? (p_out0 + (size_t)(T_ENC - 1) * U_SZ) : dh0p[d & 1];
        int lh0 = (d == 0) ? (T_ENC * U_SZ) : U_SZ;
        // layer 0: x is scalar per batch row (K0 = 1)
        lstm_step<<<grid, NTHREADS>>>(
            p_x, 1, 1, dWx0,
            h0in, lh0, U_SZ, dWh0,
            db0, p_c0, dh0p[(d & 1) ^ 1], U_SZ);
        // layer 1: input is new h0
        lstm_step<<<grid, NTHREADS>>>(
            dh0p[(d & 1) ^ 1], U_SZ, U_SZ, dWx1,
            h1p[d & 1], U_SZ, U_SZ, dWh1,
            db1, p_c1, h1p[(d + 1) & 1], U_SZ);
        // projection -> output column d and next x
        proj_kernel<<<(B_SZ * 32) / 128, 128>>>(h1p[(d + 1) & 1], Wd, bd, p_x, out, d);
    }
}